// round 1
// baseline (speedup 1.0000x reference)
#include <cuda_runtime.h>
#include <cstdint>
#include <cstddef>

// ---------------- problem constants ----------------
#define NMOD 5
#define TOKDIM 512          // [x|q|k|v] per token
#define ROWSTRIDE 2560      // NMOD * TOKDIM
#define MAXB 65536

// ---------------- static scratch (no allocs allowed) ----------------
__device__ float g_xqkv[(size_t)MAXB * ROWSTRIDE];   // [B][5][512]  x,q,k,v per token
__device__ float g_y[(size_t)MAXB * 640];            // [B][640]  post-LN fusion input
__device__ float g_W1[512 * 992];                    // merged per-modality weights
__device__ float g_b1[NMOD * 512];                   // merged biases

// ---------------- helpers ----------------
__device__ __forceinline__ uint32_t f2tf32(float x) {
    uint32_t r;
    asm("cvt.rna.tf32.f32 %0, %1;" : "=r"(r) : "f"(x));
    return r;
}

__device__ __forceinline__ void mma_tf32(float c[4], const uint32_t a[4],
                                         uint32_t b0, uint32_t b1) {
    asm volatile(
        "mma.sync.aligned.m16n8k8.row.col.f32.tf32.tf32.f32 "
        "{%0,%1,%2,%3},{%4,%5,%6,%7},{%8,%9},{%0,%1,%2,%3};"
        : "+f"(c[0]), "+f"(c[1]), "+f"(c[2]), "+f"(c[3])
        : "r"(a[0]), "r"(a[1]), "r"(a[2]), "r"(a[3]), "r"(b0), "r"(b1));
}

// ---------------- prep: W1_m = [Wm ; in_w @ Wm], b1_m = [bm ; in_w@bm + in_b] ----------------
__global__ void prep_kernel(const float* __restrict__ Wm, const float* __restrict__ bm,
                            const float* __restrict__ in_w, const float* __restrict__ in_b,
                            float* __restrict__ W1, float* __restrict__ b1, int K) {
    int K4 = K >> 2;
    int idx = blockIdx.x * blockDim.x + threadIdx.x;
    int total = 512 * K4;
    if (idx >= total) return;
    int j = idx / K4;
    int k4 = (idx - j * K4) * 4;
    float4 o;
    if (j < 128) {
        o = *reinterpret_cast<const float4*>(Wm + (size_t)j * K + k4);
    } else {
        const float* iw = in_w + (size_t)(j - 128) * 128;
        float4 a = make_float4(0.f, 0.f, 0.f, 0.f);
        for (int t = 0; t < 128; t++) {
            float w = iw[t];
            float4 v = *reinterpret_cast<const float4*>(Wm + (size_t)t * K + k4);
            a.x += w * v.x; a.y += w * v.y; a.z += w * v.z; a.w += w * v.w;
        }
        o = a;
    }
    *reinterpret_cast<float4*>(W1 + (size_t)j * K + k4) = o;
    if (k4 == 0) {
        float bb;
        if (j < 128) {
            bb = bm[j];
        } else {
            const float* iw = in_w + (size_t)(j - 128) * 128;
            float a = in_b[j - 128];
            for (int t = 0; t < 128; t++) a += iw[t] * bm[t];
            bb = a;
        }
        b1[j] = bb;
    }
}

// ---------------- generic tf32 GEMM: out[m,n] = sum_k A[m,k]*W[n,k] + bias[n] ----------------
// block tile 128x128, K tile 32, 8 warps (2x4), warp tile 64x32, double-buffered smem.
__global__ void __launch_bounds__(256) gemm_tn_kernel(
    const float* __restrict__ A, int lda,
    const float* __restrict__ W, int ldw,
    const float* __restrict__ bias,
    float* __restrict__ out, int ldo,
    int N, int K) {
    extern __shared__ float sm[];
    const int SA = 128 * 36;         // one buffer (padded stride 36 -> conflict-free frags)
    float* As = sm;                  // [2][128][36]
    float* Ws = sm + 2 * SA;         // [2][128][36]

    int tid = threadIdx.x;
    int warp = tid >> 5, lane = tid & 31;
    int wm = warp >> 2, wn = warp & 3;

    const float* Ablk = A + (size_t)blockIdx.x * 128 * lda;
    int nbase = blockIdx.y * 128;
    const float* Wblk = W + (size_t)nbase * ldw;

    float acc[4][4][4];
#pragma unroll
    for (int i = 0; i < 4; i++)
#pragma unroll
        for (int j = 0; j < 4; j++)
#pragma unroll
            for (int q = 0; q < 4; q++) acc[i][j][q] = 0.f;

    int lrow = tid >> 3;          // 0..31
    int lc4 = (tid & 7) * 4;      // 0..28

    int nkt = K / 32;

    auto loadTiles = [&](int kt, int buf) {
        int k0 = kt * 32;
#pragma unroll
        for (int p = 0; p < 4; p++) {
            int r = lrow + p * 32;
            float4 va = *reinterpret_cast<const float4*>(Ablk + (size_t)r * lda + k0 + lc4);
            uint32_t* da = reinterpret_cast<uint32_t*>(As + buf * SA + r * 36 + lc4);
            da[0] = f2tf32(va.x); da[1] = f2tf32(va.y); da[2] = f2tf32(va.z); da[3] = f2tf32(va.w);
            float4 vw = make_float4(0.f, 0.f, 0.f, 0.f);
            if (nbase + r < N)
                vw = *reinterpret_cast<const float4*>(Wblk + (size_t)r * ldw + k0 + lc4);
            uint32_t* dw = reinterpret_cast<uint32_t*>(Ws + buf * SA + r * 36 + lc4);
            dw[0] = f2tf32(vw.x); dw[1] = f2tf32(vw.y); dw[2] = f2tf32(vw.z); dw[3] = f2tf32(vw.w);
        }
    };

    loadTiles(0, 0);
    __syncthreads();

    int ar = wm * 64 + (lane >> 2);
    int br = wn * 32 + (lane >> 2);
    int kc = lane & 3;

    for (int kt = 0; kt < nkt; kt++) {
        int buf = kt & 1;
        if (kt + 1 < nkt) loadTiles(kt + 1, buf ^ 1);
        const float* Ab = As + buf * SA;
        const float* Wb = Ws + buf * SA;
#pragma unroll
        for (int kk = 0; kk < 4; kk++) {
            uint32_t af[4][4];
#pragma unroll
            for (int mf = 0; mf < 4; mf++) {
                const uint32_t* p0 = reinterpret_cast<const uint32_t*>(Ab + (ar + mf * 16) * 36 + kk * 8 + kc);
                const uint32_t* p1 = reinterpret_cast<const uint32_t*>(Ab + (ar + mf * 16 + 8) * 36 + kk * 8 + kc);
                af[mf][0] = p0[0]; af[mf][1] = p1[0]; af[mf][2] = p0[4]; af[mf][3] = p1[4];
            }
#pragma unroll
            for (int nf = 0; nf < 4; nf++) {
                const uint32_t* pb = reinterpret_cast<const uint32_t*>(Wb + (br + nf * 8) * 36 + kk * 8 + kc);
                uint32_t b0 = pb[0], b1 = pb[4];
#pragma unroll
                for (int mf = 0; mf < 4; mf++) mma_tf32(acc[mf][nf], af[mf], b0, b1);
            }
        }
        __syncthreads();
    }

    int rbase = blockIdx.x * 128 + wm * 64 + (lane >> 2);
#pragma unroll
    for (int mf = 0; mf < 4; mf++) {
#pragma unroll
        for (int nf = 0; nf < 4; nf++) {
            int col = nbase + wn * 32 + nf * 8 + 2 * (lane & 3);
            int r0 = rbase + mf * 16;
            if (col < N) {
                float bv = bias[col];
                out[(size_t)r0 * ldo + col] = acc[mf][nf][0] + bv;
                out[(size_t)(r0 + 8) * ldo + col] = acc[mf][nf][2] + bv;
            }
            if (col + 1 < N) {
                float bv = bias[col + 1];
                out[(size_t)r0 * ldo + col + 1] = acc[mf][nf][1] + bv;
                out[(size_t)(r0 + 8) * ldo + col + 1] = acc[mf][nf][3] + bv;
            }
        }
    }
}

// ---------------- fused attention + out-proj + residual + LayerNorm ----------------
// one CTA = 32 samples (160 token-rows). scores/softmax/ctx SIMT (5 tokens -> tiny),
// out-projection via tf32 mma strips over shared ctx tile, then LN epilogue -> g_y.
__global__ void __launch_bounds__(256) attn_kernel(
    const float* __restrict__ out_w, const float* __restrict__ out_b,
    const float* __restrict__ ln_g, const float* __restrict__ ln_b) {
    extern __shared__ float sm[];
    float* s_ctx = sm;               // [160][132]  ctx (tf32 bits) -> reused as attn_out
    float* s_w = sm + 160 * 132;     // [128][132]  out_w (tf32 bits)

    int tid = threadIdx.x, warp = tid >> 5, lane = tid & 31;
    int S0 = blockIdx.x * 32;

    // stage out_w (tf32-rounded)
    for (int idx = tid; idx < 128 * 32; idx += 256) {
        int r = idx >> 5;
        int c4 = (idx & 31) * 4;
        float4 v = *reinterpret_cast<const float4*>(out_w + (size_t)r * 128 + c4);
        uint32_t* d = reinterpret_cast<uint32_t*>(s_w + r * 132 + c4);
        d[0] = f2tf32(v.x); d[1] = f2tf32(v.y); d[2] = f2tf32(v.z); d[3] = f2tf32(v.w);
    }

    // scores + softmax + ctx, 4 samples per warp
#pragma unroll
    for (int t = 0; t < 4; t++) {
        int sl = warp * 4 + t;
        int s = S0 + sl;
        const float* base = g_xqkv + (size_t)s * ROWSTRIDE;
        float attn[5] = {0.f, 0.f, 0.f, 0.f, 0.f};
        if (lane < 20) {
            int h = lane / 5, i = lane % 5;
            float qv[32];
            const float4* qp = reinterpret_cast<const float4*>(base + i * 512 + 128 + h * 32);
#pragma unroll
            for (int u = 0; u < 8; u++) {
                float4 f = qp[u];
                qv[4 * u] = f.x; qv[4 * u + 1] = f.y; qv[4 * u + 2] = f.z; qv[4 * u + 3] = f.w;
            }
            float sc[5];
#pragma unroll
            for (int j = 0; j < 5; j++) {
                const float4* kp = reinterpret_cast<const float4*>(base + j * 512 + 256 + h * 32);
                float a = 0.f;
#pragma unroll
                for (int u = 0; u < 8; u++) {
                    float4 f = kp[u];
                    a += qv[4 * u] * f.x + qv[4 * u + 1] * f.y + qv[4 * u + 2] * f.z + qv[4 * u + 3] * f.w;
                }
                sc[j] = a * 0.17677669529663687f;  // 1/sqrt(32)
            }
            float mx = sc[0];
#pragma unroll
            for (int j = 1; j < 5; j++) mx = fmaxf(mx, sc[j]);
            float den = 0.f;
#pragma unroll
            for (int j = 0; j < 5; j++) { attn[j] = __expf(sc[j] - mx); den += attn[j]; }
            float inv = 1.f / den;
#pragma unroll
            for (int j = 0; j < 5; j++) attn[j] *= inv;
        }
        __syncwarp();
        int h2 = lane >> 3;       // head of the 4 cols this lane owns
        int c4 = lane * 4;
#pragma unroll
        for (int i = 0; i < 5; i++) {
            float ax = 0.f, ay = 0.f, az = 0.f, aw = 0.f;
#pragma unroll
            for (int j = 0; j < 5; j++) {
                float a = __shfl_sync(0xffffffffu, attn[j], h2 * 5 + i);
                float4 v = *reinterpret_cast<const float4*>(base + j * 512 + 384 + c4);
                ax += a * v.x; ay += a * v.y; az += a * v.z; aw += a * v.w;
            }
            uint32_t* d = reinterpret_cast<uint32_t*>(s_ctx + (sl * 5 + i) * 132 + c4);
            d[0] = f2tf32(ax); d[1] = f2tf32(ay); d[2] = f2tf32(az); d[3] = f2tf32(aw);
        }
    }
    __syncthreads();

    // out-projection: 10 strips of 16 rows, each warp owns strips warp, warp+8
    for (int strip = warp; strip < 10; strip += 8) {
        float acc[16][4];
#pragma unroll
        for (int nf = 0; nf < 16; nf++) {
            acc[nf][0] = 0.f; acc[nf][1] = 0.f; acc[nf][2] = 0.f; acc[nf][3] = 0.f;
        }
        int ar = strip * 16 + (lane >> 2);
        int kc = lane & 3;
#pragma unroll 4
        for (int kk = 0; kk < 16; kk++) {
            uint32_t af[4];
            const uint32_t* p0 = reinterpret_cast<const uint32_t*>(s_ctx + ar * 132 + kk * 8 + kc);
            const uint32_t* p1 = reinterpret_cast<const uint32_t*>(s_ctx + (ar + 8) * 132 + kk * 8 + kc);
            af[0] = p0[0]; af[1] = p1[0]; af[2] = p0[4]; af[3] = p1[4];
#pragma unroll
            for (int nf = 0; nf < 16; nf++) {
                const uint32_t* pb = reinterpret_cast<const uint32_t*>(s_w + (nf * 8 + (lane >> 2)) * 132 + kk * 8 + kc);
                mma_tf32(acc[nf], af, pb[0], pb[4]);
            }
        }
        __syncwarp();  // all lanes done reading s_ctx rows before in-place overwrite
#pragma unroll
        for (int nf = 0; nf < 16; nf++) {
            int col = nf * 8 + 2 * (lane & 3);
            float b0 = out_b[col], b1 = out_b[col + 1];
            int r0 = strip * 16 + (lane >> 2);
            s_ctx[r0 * 132 + col] = acc[nf][0] + b0;
            s_ctx[r0 * 132 + col + 1] = acc[nf][1] + b1;
            s_ctx[(r0 + 8) * 132 + col] = acc[nf][2] + b0;
            s_ctx[(r0 + 8) * 132 + col + 1] = acc[nf][3] + b1;
        }
    }
    __syncthreads();

    // residual + LayerNorm -> g_y
    for (int r = warp; r < 160; r += 8) {
        int s = S0 + r / 5;
        int tok = r - (r / 5) * 5;
        float4 v = *reinterpret_cast<float4*>(s_ctx + r * 132 + lane * 4);
        float4 x4 = *reinterpret_cast<const float4*>(g_xqkv + (size_t)s * ROWSTRIDE + tok * 512 + lane * 4);
        v.x += x4.x; v.y += x4.y; v.z += x4.z; v.w += x4.w;
        float sum = v.x + v.y + v.z + v.w;
        float sq = v.x * v.x + v.y * v.y + v.z * v.z + v.w * v.w;
#pragma unroll
        for (int o = 16; o > 0; o >>= 1) {
            sum += __shfl_xor_sync(0xffffffffu, sum, o);
            sq += __shfl_xor_sync(0xffffffffu, sq, o);
        }
        float mu = sum * (1.f / 128.f);
        float var = sq * (1.f / 128.f) - mu * mu;
        float rs = rsqrtf(var + 1e-5f);
        float4 g4 = *reinterpret_cast<const float4*>(ln_g + lane * 4);
        float4 b4 = *reinterpret_cast<const float4*>(ln_b + lane * 4);
        float4 y;
        y.x = (v.x - mu) * rs * g4.x + b4.x;
        y.y = (v.y - mu) * rs * g4.y + b4.y;
        y.z = (v.z - mu) * rs * g4.z + b4.z;
        y.w = (v.w - mu) * rs * g4.w + b4.w;
        *reinterpret_cast<float4*>(g_y + (size_t)s * 640 + tok * 128 + lane * 4) = y;
    }
}

// ---------------- launcher ----------------
extern "C" void kernel_launch(void* const* d_in, const int* in_sizes, int n_in,
                              void* d_out, int out_size) {
    const float* cat    = (const float*)d_in[0];
    const float* menu   = (const float*)d_in[1];
    const float* diner  = (const float*)d_in[2];
    const float* price  = (const float*)d_in[3];
    const float* review = (const float*)d_in[4];
    const float* Wc = (const float*)d_in[5];  const float* bc = (const float*)d_in[6];
    const float* Wm = (const float*)d_in[7];  const float* bm = (const float*)d_in[8];
    const float* Wd = (const float*)d_in[9];  const float* bd = (const float*)d_in[10];
    const float* Wp = (const float*)d_in[11]; const float* bp = (const float*)d_in[12];
    const float* Wr = (const float*)d_in[13]; const float* br = (const float*)d_in[14];
    const float* in_w = (const float*)d_in[15];  const float* in_b = (const float*)d_in[16];
    const float* out_w = (const float*)d_in[17]; const float* out_b = (const float*)d_in[18];
    const float* ln_g = (const float*)d_in[19];  const float* ln_b = (const float*)d_in[20];
    const float* fus_w = (const float*)d_in[21]; const float* fus_b = (const float*)d_in[22];

    int B = in_sizes[0] / 128;

    float *xqkv, *y, *W1, *b1;
    cudaGetSymbolAddress((void**)&xqkv, g_xqkv);
    cudaGetSymbolAddress((void**)&y, g_y);
    cudaGetSymbolAddress((void**)&W1, g_W1);
    cudaGetSymbolAddress((void**)&b1, g_b1);

    const int gemm_smem = 4 * 128 * 36 * (int)sizeof(float);           // 73728
    const int attn_smem = (160 + 128) * 132 * (int)sizeof(float);      // 152064
    cudaFuncSetAttribute(gemm_tn_kernel, cudaFuncAttributeMaxDynamicSharedMemorySize, gemm_smem);
    cudaFuncSetAttribute(attn_kernel, cudaFuncAttributeMaxDynamicSharedMemorySize, attn_smem);

    const int Ks[5] = {128, 256, 64, 32, 512};
    const int offs[5] = {0, 512 * 128, 512 * 384, 512 * 448, 512 * 480};
    const float* Es[5] = {cat, menu, diner, price, review};
    const float* Wmods[5] = {Wc, Wm, Wd, Wp, Wr};
    const float* bmods[5] = {bc, bm, bd, bp, br};

    for (int m = 0; m < 5; m++) {
        int total = 512 * (Ks[m] / 4);
        prep_kernel<<<(total + 255) / 256, 256>>>(Wmods[m], bmods[m], in_w, in_b,
                                                  W1 + offs[m], b1 + m * 512, Ks[m]);
    }
    for (int m = 0; m < 5; m++) {
        dim3 grid(B / 128, 4);
        gemm_tn_kernel<<<grid, 256, gemm_smem>>>(Es[m], Ks[m], W1 + offs[m], Ks[m],
                                                 b1 + m * 512, xqkv + m * 512, ROWSTRIDE,
                                                 512, Ks[m]);
    }
    attn_kernel<<<B / 32, 256, attn_smem>>>(out_w, out_b, ln_g, ln_b);
    {
        dim3 grid(B / 128, 8);
        gemm_tn_kernel<<<grid, 256, gemm_smem>>>(y, 640, fus_w, 640, fus_b,
                                                 (float*)d_out, 992, 992, 640);
    }
}